// round 12
// baseline (speedup 1.0000x reference)
#include <cuda_runtime.h>
#include <math_constants.h>

#define BB 16
#define CC 256
#define RR 64
#define HW 16384
#define HW4 (HW / 4)                 // 4096 float4 per plane per component
#define HALF4 (HW4 / 2)              // 2048 float4 per half-plane
#define NPLANE (BB * CC)             // 4096
#define NHALF (NPLANE * 2)           // 8192 half-planes
#define NEG_SLOPE 0.01f

// Scratch (__device__ globals; allocation-free rule)
__device__ float g_hsr[NHALF], g_hsi[NHALF];   // half-plane sums
__device__ float g_hmr[NHALF], g_hmi[NHALF];   // half-plane maxes
__device__ float g_gr[NPLANE], g_gi[NPLANE];   // gates

// ---------------------------------------------------------------------------
// Kernel 1: per-HALF-plane mean + max pooling (R9 verbatim: 78us @ 87.7%).
// No atomics, no fences — launch boundary publishes the partials.
// ---------------------------------------------------------------------------
__global__ __launch_bounds__(256) void pool_kernel(const float* __restrict__ xr,
                                                   const float* __restrict__ xi) {
    const int hp = blockIdx.x;                       // half-plane id
    const size_t base = (size_t)hp * HALF4;
    const float4* pr = reinterpret_cast<const float4*>(xr) + base;
    const float4* pi = reinterpret_cast<const float4*>(xi) + base;

    float sr = 0.f, si = 0.f;
    float mr = -CUDART_INF_F, mi = -CUDART_INF_F;

#pragma unroll
    for (int it = 0; it < HALF4 / 256; it++) {       // 8 iters
        const int i = it * 256 + threadIdx.x;
        float4 a = pr[i];
        float4 b = pi[i];
        sr += (a.x + a.y) + (a.z + a.w);
        si += (b.x + b.y) + (b.z + b.w);
        mr = fmaxf(mr, fmaxf(fmaxf(a.x, a.y), fmaxf(a.z, a.w)));
        mi = fmaxf(mi, fmaxf(fmaxf(b.x, b.y), fmaxf(b.z, b.w)));
    }
#pragma unroll
    for (int o = 16; o > 0; o >>= 1) {
        sr += __shfl_down_sync(0xFFFFFFFFu, sr, o);
        si += __shfl_down_sync(0xFFFFFFFFu, si, o);
        mr = fmaxf(mr, __shfl_down_sync(0xFFFFFFFFu, mr, o));
        mi = fmaxf(mi, __shfl_down_sync(0xFFFFFFFFu, mi, o));
    }
    __shared__ float s_sr[8], s_si[8], s_mr[8], s_mi[8];
    const int wid = threadIdx.x >> 5;
    const int lid = threadIdx.x & 31;
    if (lid == 0) { s_sr[wid] = sr; s_si[wid] = si; s_mr[wid] = mr; s_mi[wid] = mi; }
    __syncthreads();
    if (threadIdx.x == 0) {
        float tsr = s_sr[0], tsi = s_si[0], tmr = s_mr[0], tmi = s_mi[0];
#pragma unroll
        for (int w = 1; w < 8; w++) {
            tsr += s_sr[w]; tsi += s_si[w];
            tmr = fmaxf(tmr, s_mr[w]); tmi = fmaxf(tmi, s_mi[w]);
        }
        g_hsr[hp] = tsr; g_hsi[hp] = tsi;
        g_hmr[hp] = tmr; g_hmi[hp] = tmi;
    }
}

// ---------------------------------------------------------------------------
// Kernel 2: gate MLP (coalesced warp-per-output). One block per batch, ~5us.
// ---------------------------------------------------------------------------
__global__ __launch_bounds__(256) void gate_kernel(
    const float* __restrict__ w1r, const float* __restrict__ w1i,
    const float* __restrict__ b1r, const float* __restrict__ b1i,
    const float* __restrict__ w2r, const float* __restrict__ w2i,
    const float* __restrict__ b2r, const float* __restrict__ b2i) {
    const int b = blockIdx.x;
    const int tid = threadIdx.x;
    const int wid = tid >> 5;
    const int lane = tid & 31;

    __shared__ float s_in[4][CC];   // avg_r, avg_i, max_r, max_i
    __shared__ float s_h[4][RR];    // hidden (post-LeakyReLU)

    {   // combine half-plane partials -> pooled per-channel values
        const int h0 = (b * CC + tid) * 2;
        s_in[0][tid] = (g_hsr[h0] + g_hsr[h0 + 1]) * (1.0f / HW);
        s_in[1][tid] = (g_hsi[h0] + g_hsi[h0 + 1]) * (1.0f / HW);
        s_in[2][tid] = fmaxf(g_hmr[h0], g_hmr[h0 + 1]);
        s_in[3][tid] = fmaxf(g_hmi[h0], g_hmi[h0 + 1]);
    }
    __syncthreads();

#pragma unroll
    for (int i = 0; i < 16; i++) {   // layer 1: 128 outputs, 16 per warp
        const int o = wid * 16 + i;
        const int which = o >> 6;
        const int r = o & (RR - 1);
        const float* zr = s_in[2 * which];
        const float* zi = s_in[2 * which + 1];
        float yr = 0.f, yi = 0.f;
#pragma unroll
        for (int cc = 0; cc < CC / 32; cc++) {   // 8 coalesced iterations
            const int c = cc * 32 + lane;
            const float wr = w1r[r * CC + c];
            const float wi = w1i[r * CC + c];
            const float zrc = zr[c], zic = zi[c];
            yr = fmaf(zrc, wr, fmaf(-zic, wi, yr));
            yi = fmaf(zrc, wi, fmaf(zic, wr, yi));
        }
#pragma unroll
        for (int o2 = 16; o2 > 0; o2 >>= 1) {
            yr += __shfl_down_sync(0xFFFFFFFFu, yr, o2);
            yi += __shfl_down_sync(0xFFFFFFFFu, yi, o2);
        }
        if (lane == 0) {
            yr += b1r[r]; yi += b1i[r];
            yr = (yr > 0.f) ? yr : NEG_SLOPE * yr;
            yi = (yi > 0.f) ? yi : NEG_SLOPE * yi;
            s_h[2 * which][r] = yr;
            s_h[2 * which + 1][r] = yi;
        }
    }
    __syncthreads();

#pragma unroll
    for (int i = 0; i < 32; i++) {   // layer 2: 256 channels, 32 per warp
        const int t = wid * 32 + i;
        float ar = 0.f, ai = 0.f, mr2 = 0.f, mi2 = 0.f;
#pragma unroll
        for (int jj = 0; jj < RR / 32; jj++) {   // 2 coalesced iterations
            const int j = jj * 32 + lane;
            const float wr = w2r[t * RR + j];
            const float wi = w2i[t * RR + j];
            const float har = s_h[0][j], hai = s_h[1][j];
            const float hmr = s_h[2][j], hmi = s_h[3][j];
            ar  = fmaf(har, wr, fmaf(-hai, wi, ar));
            ai  = fmaf(har, wi, fmaf(hai, wr, ai));
            mr2 = fmaf(hmr, wr, fmaf(-hmi, wi, mr2));
            mi2 = fmaf(hmr, wi, fmaf(hmi, wr, mi2));
        }
#pragma unroll
        for (int o2 = 16; o2 > 0; o2 >>= 1) {
            ar  += __shfl_down_sync(0xFFFFFFFFu, ar, o2);
            ai  += __shfl_down_sync(0xFFFFFFFFu, ai, o2);
            mr2 += __shfl_down_sync(0xFFFFFFFFu, mr2, o2);
            mi2 += __shfl_down_sync(0xFFFFFFFFu, mi2, o2);
        }
        if (lane == 0) {
            const float zr = (ar + b2r[t]) + (mr2 + b2r[t]);
            const float zi = (ai + b2i[t]) + (mi2 + b2i[t]);
            g_gr[b * CC + t] = 1.0f / (1.0f + expf(-zr));
            g_gi[b * CC + t] = 1.0f / (1.0f + expf(-zi));
        }
    }
}

// ---------------------------------------------------------------------------
// Kernel 3: complex multiply x * gate -> out[2,B,C,H,W]  (R11 verbatim:
// 154.6us @ 83.2% DRAM). Reverse half-plane order for L2-tail reuse; plain
// loads (hit resident tail); __stcs stores (no write-allocate -> reads stay
// L2-resident; measured: DRAM traffic ~= write volume only).
// ---------------------------------------------------------------------------
__global__ __launch_bounds__(256) void apply_kernel(const float* __restrict__ xr,
                                                    const float* __restrict__ xi,
                                                    float* __restrict__ out) {
    const int blk = (NHALF - 1) - blockIdx.x;        // reverse half-plane order
    const int plane = blk >> 1;
    const float gr = g_gr[plane];
    const float gi = g_gi[plane];

    const size_t base = (size_t)blk * HALF4;
    const float4* pr = reinterpret_cast<const float4*>(xr) + base;
    const float4* pi = reinterpret_cast<const float4*>(xi) + base;
    float4* po_r = reinterpret_cast<float4*>(out) + base;
    float4* po_i = reinterpret_cast<float4*>(out) + (size_t)NPLANE * HW4 + base;

#pragma unroll
    for (int it = 0; it < HALF4 / 256; it++) {       // 8 iters
        const int i = it * 256 + threadIdx.x;
        float4 a = pr[i];
        float4 b = pi[i];
        float4 r, m;
        r.x = fmaf(a.x, gr, -b.x * gi);
        r.y = fmaf(a.y, gr, -b.y * gi);
        r.z = fmaf(a.z, gr, -b.z * gi);
        r.w = fmaf(a.w, gr, -b.w * gi);
        m.x = fmaf(a.x, gi, b.x * gr);
        m.y = fmaf(a.y, gi, b.y * gr);
        m.z = fmaf(a.z, gi, b.z * gr);
        m.w = fmaf(a.w, gi, b.w * gr);
        __stcs(po_r + i, r);                          // evict-first writes
        __stcs(po_i + i, m);
    }
}

extern "C" void kernel_launch(void* const* d_in, const int* in_sizes, int n_in,
                              void* d_out, int out_size) {
    const float* xr  = (const float*)d_in[0];
    const float* xi  = (const float*)d_in[1];
    const float* w1r = (const float*)d_in[2];
    const float* w1i = (const float*)d_in[3];
    const float* b1r = (const float*)d_in[4];
    const float* b1i = (const float*)d_in[5];
    const float* w2r = (const float*)d_in[6];
    const float* w2i = (const float*)d_in[7];
    const float* b2r = (const float*)d_in[8];
    const float* b2i = (const float*)d_in[9];
    float* out = (float*)d_out;

    pool_kernel<<<NHALF, 256>>>(xr, xi);
    gate_kernel<<<BB, 256>>>(w1r, w1i, b1r, b1i, w2r, w2i, b2r, b2i);
    apply_kernel<<<NHALF, 256>>>(xr, xi, out);
}

// round 13
// speedup vs baseline: 1.0981x; 1.0981x over previous
#include <cuda_runtime.h>
#include <math_constants.h>

#define BB 16
#define CC 256
#define RR 64
#define HW 16384
#define HW4 (HW / 4)                 // 4096 float4 per plane per component
#define HALF4 (HW4 / 2)              // 2048 float4 per half-plane
#define NPLANE (BB * CC)             // 4096
#define NHALF (NPLANE * 2)           // 8192 half-planes
#define HALF_PER_BATCH (CC * 2)      // 512 half-planes per batch
#define NEG_SLOPE 0.01f

// Scratch (__device__ globals; allocation-free rule).
// g_cnt zero-initialized at load; finisher self-resets its slot each launch.
__device__ float g_hsr[NHALF], g_hsi[NHALF];   // half-plane sums
__device__ float g_hmr[NHALF], g_hmi[NHALF];   // half-plane maxes
__device__ float g_gr[NPLANE], g_gi[NPLANE];   // gates
__device__ int   g_cnt[BB];                    // per-batch completion counters

// acq_rel RMW: release = publishes this thread's prior stores (the partials);
// acquire = synchronizes-with all earlier releases on the same counter, so the
// winning (finisher) thread observes every block's partials. Avoids the
// per-block __threadfence() -> CCTL.IVALL L1-flush + MEMBAR cost.
__device__ __forceinline__ int atomic_add_acq_rel(int* p, int v) {
    int old;
    asm volatile("atom.acq_rel.gpu.global.add.s32 %0, [%1], %2;"
                 : "=r"(old) : "l"(p), "r"(v) : "memory");
    return old;
}

// ---------------------------------------------------------------------------
// Kernel 1: per-HALF-plane mean+max pooling; the block completing a batch's
// 512th half-plane computes that batch's gate MLP inline (coalesced, hidden
// under remaining pool traffic), then resets the batch counter.
// __launch_bounds__(256,6): cap at 42 regs so the hot pool path (38 regs
// measured) keeps occupancy; the rare MLP path may spill (16/8192 blocks).
// ---------------------------------------------------------------------------
__global__ __launch_bounds__(256, 6) void pool_gate_kernel(
    const float* __restrict__ xr, const float* __restrict__ xi,
    const float* __restrict__ w1r, const float* __restrict__ w1i,
    const float* __restrict__ b1r, const float* __restrict__ b1i,
    const float* __restrict__ w2r, const float* __restrict__ w2i,
    const float* __restrict__ b2r, const float* __restrict__ b2i) {
    const int hp = blockIdx.x;                       // half-plane id
    const int batch = hp / HALF_PER_BATCH;
    const int tid = threadIdx.x;
    const int wid = tid >> 5;
    const int lane = tid & 31;

    {   // ---------------- pooling ----------------
        const size_t base = (size_t)hp * HALF4;
        const float4* pr = reinterpret_cast<const float4*>(xr) + base;
        const float4* pi = reinterpret_cast<const float4*>(xi) + base;

        float sr = 0.f, si = 0.f;
        float mr = -CUDART_INF_F, mi = -CUDART_INF_F;
#pragma unroll
        for (int it = 0; it < HALF4 / 256; it++) {   // 8 iters
            const int i = it * 256 + tid;
            float4 a = pr[i];
            float4 b = pi[i];
            sr += (a.x + a.y) + (a.z + a.w);
            si += (b.x + b.y) + (b.z + b.w);
            mr = fmaxf(mr, fmaxf(fmaxf(a.x, a.y), fmaxf(a.z, a.w)));
            mi = fmaxf(mi, fmaxf(fmaxf(b.x, b.y), fmaxf(b.z, b.w)));
        }
#pragma unroll
        for (int o = 16; o > 0; o >>= 1) {
            sr += __shfl_down_sync(0xFFFFFFFFu, sr, o);
            si += __shfl_down_sync(0xFFFFFFFFu, si, o);
            mr = fmaxf(mr, __shfl_down_sync(0xFFFFFFFFu, mr, o));
            mi = fmaxf(mi, __shfl_down_sync(0xFFFFFFFFu, mi, o));
        }
        __shared__ float s_sr[8], s_si[8], s_mr[8], s_mi[8];
        if (lane == 0) { s_sr[wid] = sr; s_si[wid] = si; s_mr[wid] = mr; s_mi[wid] = mi; }
        __syncthreads();
        if (tid == 0) {
            float tsr = s_sr[0], tsi = s_si[0], tmr = s_mr[0], tmi = s_mi[0];
#pragma unroll
            for (int w = 1; w < 8; w++) {
                tsr += s_sr[w]; tsi += s_si[w];
                tmr = fmaxf(tmr, s_mr[w]); tmi = fmaxf(tmi, s_mi[w]);
            }
            g_hsr[hp] = tsr; g_hsi[hp] = tsi;
            g_hmr[hp] = tmr; g_hmi[hp] = tmi;
        }
    }

    // ---------------- finisher election (acq_rel, no threadfence) ----------
    __shared__ int s_fin;
    __syncthreads();               // pool smem writes done before reuse below
    if (tid == 0) {
        // tid 0 wrote this block's partials above; release publishes them.
        s_fin = (atomic_add_acq_rel(&g_cnt[batch], 1) == HALF_PER_BATCH - 1);
    }
    __syncthreads();               // broadcasts s_fin AND extends tid0's acquire
    if (!s_fin) return;

    // Last toucher of g_cnt[batch] this launch; reset for next graph replay.
    if (tid == 0) g_cnt[batch] = 0;

    // ---------------- gate MLP for `batch` (coalesced, proven) -------------
    __shared__ float s_in[4][CC];
    __shared__ float s_h[4][RR];
    {
        const int h0 = (batch * CC + tid) * 2;
        s_in[0][tid] = (g_hsr[h0] + g_hsr[h0 + 1]) * (1.0f / HW);
        s_in[1][tid] = (g_hsi[h0] + g_hsi[h0 + 1]) * (1.0f / HW);
        s_in[2][tid] = fmaxf(g_hmr[h0], g_hmr[h0 + 1]);
        s_in[3][tid] = fmaxf(g_hmi[h0], g_hmi[h0 + 1]);
    }
    __syncthreads();

#pragma unroll
    for (int i = 0; i < 16; i++) {   // layer 1: 128 outputs, 16 per warp
        const int o = wid * 16 + i;
        const int which = o >> 6;
        const int r = o & (RR - 1);
        const float* zr = s_in[2 * which];
        const float* zi = s_in[2 * which + 1];
        float yr = 0.f, yi = 0.f;
#pragma unroll
        for (int cc = 0; cc < CC / 32; cc++) {
            const int c = cc * 32 + lane;
            const float wr = w1r[r * CC + c];
            const float wi = w1i[r * CC + c];
            const float zrc = zr[c], zic = zi[c];
            yr = fmaf(zrc, wr, fmaf(-zic, wi, yr));
            yi = fmaf(zrc, wi, fmaf(zic, wr, yi));
        }
#pragma unroll
        for (int o2 = 16; o2 > 0; o2 >>= 1) {
            yr += __shfl_down_sync(0xFFFFFFFFu, yr, o2);
            yi += __shfl_down_sync(0xFFFFFFFFu, yi, o2);
        }
        if (lane == 0) {
            yr += b1r[r]; yi += b1i[r];
            yr = (yr > 0.f) ? yr : NEG_SLOPE * yr;
            yi = (yi > 0.f) ? yi : NEG_SLOPE * yi;
            s_h[2 * which][r] = yr;
            s_h[2 * which + 1][r] = yi;
        }
    }
    __syncthreads();

#pragma unroll
    for (int i = 0; i < 32; i++) {   // layer 2: 256 channels, 32 per warp
        const int t = wid * 32 + i;
        float ar = 0.f, ai = 0.f, mr2 = 0.f, mi2 = 0.f;
#pragma unroll
        for (int jj = 0; jj < RR / 32; jj++) {
            const int j = jj * 32 + lane;
            const float wr = w2r[t * RR + j];
            const float wi = w2i[t * RR + j];
            const float har = s_h[0][j], hai = s_h[1][j];
            const float hmr = s_h[2][j], hmi = s_h[3][j];
            ar  = fmaf(har, wr, fmaf(-hai, wi, ar));
            ai  = fmaf(har, wi, fmaf(hai, wr, ai));
            mr2 = fmaf(hmr, wr, fmaf(-hmi, wi, mr2));
            mi2 = fmaf(hmr, wi, fmaf(hmi, wr, mi2));
        }
#pragma unroll
        for (int o2 = 16; o2 > 0; o2 >>= 1) {
            ar  += __shfl_down_sync(0xFFFFFFFFu, ar, o2);
            ai  += __shfl_down_sync(0xFFFFFFFFu, ai, o2);
            mr2 += __shfl_down_sync(0xFFFFFFFFu, mr2, o2);
            mi2 += __shfl_down_sync(0xFFFFFFFFu, mi2, o2);
        }
        if (lane == 0) {
            const float zr = (ar + b2r[t]) + (mr2 + b2r[t]);
            const float zi = (ai + b2i[t]) + (mi2 + b2i[t]);
            g_gr[batch * CC + t] = 1.0f / (1.0f + expf(-zr));
            g_gi[batch * CC + t] = 1.0f / (1.0f + expf(-zi));
        }
    }
    // consumed by apply_kernel; launch boundary = barrier
}

// ---------------------------------------------------------------------------
// Kernel 2: complex multiply x * gate -> out[2,B,C,H,W]  (measured 154.6us @
// 83.2% DRAM). Reverse half-plane order for L2-tail reuse; plain loads (hit
// resident tail); __stcs stores (no write-allocate -> reads stay L2-resident).
// ---------------------------------------------------------------------------
__global__ __launch_bounds__(256) void apply_kernel(const float* __restrict__ xr,
                                                    const float* __restrict__ xi,
                                                    float* __restrict__ out) {
    const int blk = (NHALF - 1) - blockIdx.x;        // reverse half-plane order
    const int plane = blk >> 1;
    const float gr = g_gr[plane];
    const float gi = g_gi[plane];

    const size_t base = (size_t)blk * HALF4;
    const float4* pr = reinterpret_cast<const float4*>(xr) + base;
    const float4* pi = reinterpret_cast<const float4*>(xi) + base;
    float4* po_r = reinterpret_cast<float4*>(out) + base;
    float4* po_i = reinterpret_cast<float4*>(out) + (size_t)NPLANE * HW4 + base;

#pragma unroll
    for (int it = 0; it < HALF4 / 256; it++) {       // 8 iters
        const int i = it * 256 + threadIdx.x;
        float4 a = pr[i];
        float4 b = pi[i];
        float4 r, m;
        r.x = fmaf(a.x, gr, -b.x * gi);
        r.y = fmaf(a.y, gr, -b.y * gi);
        r.z = fmaf(a.z, gr, -b.z * gi);
        r.w = fmaf(a.w, gr, -b.w * gi);
        m.x = fmaf(a.x, gi, b.x * gr);
        m.y = fmaf(a.y, gi, b.y * gr);
        m.z = fmaf(a.z, gi, b.z * gr);
        m.w = fmaf(a.w, gi, b.w * gr);
        __stcs(po_r + i, r);                          // evict-first writes
        __stcs(po_i + i, m);
    }
}

extern "C" void kernel_launch(void* const* d_in, const int* in_sizes, int n_in,
                              void* d_out, int out_size) {
    const float* xr  = (const float*)d_in[0];
    const float* xi  = (const float*)d_in[1];
    const float* w1r = (const float*)d_in[2];
    const float* w1i = (const float*)d_in[3];
    const float* b1r = (const float*)d_in[4];
    const float* b1i = (const float*)d_in[5];
    const float* w2r = (const float*)d_in[6];
    const float* w2i = (const float*)d_in[7];
    const float* b2r = (const float*)d_in[8];
    const float* b2i = (const float*)d_in[9];
    float* out = (float*)d_out;

    pool_gate_kernel<<<NHALF, 256>>>(xr, xi,
                                     w1r, w1i, b1r, b1i,
                                     w2r, w2i, b2r, b2i);
    apply_kernel<<<NHALF, 256>>>(xr, xi, out);
}